// round 12
// baseline (speedup 1.0000x reference)
#include <cuda_runtime.h>
#include <cuda_bf16.h>
#include <cstdint>

#define BB 8192
#define LL 256
#define BPSET 32                     // batches per set (fwd warp + bwd warp, 2 per lane-pair)
#define SETS 2                       // 4 warps/block -> all SMSPs
#define BPBLK (BPSET * SETS)         // 64
#define GRAN 10                      // float4 granules per batch row per group (9 data + 1 slack)
#define ROWB (GRAN * 16)             // 160 B
#define BUF_BYTES (BPSET * ROWB)     // 5120 B
#define NBUF 2

static __device__ __forceinline__ unsigned long long pk2(float lo, float hi) {
    unsigned long long r; asm("mov.b64 %0, {%1,%2};" : "=l"(r) : "f"(lo), "f"(hi)); return r;
}
static __device__ __forceinline__ void upk2(float& lo, float& hi, unsigned long long v) {
    asm("mov.b64 {%0,%1}, %2;" : "=f"(lo), "=f"(hi) : "l"(v));
}
static __device__ __forceinline__ unsigned long long fma2_(unsigned long long a, unsigned long long b, unsigned long long c) {
    unsigned long long d; asm("fma.rn.f32x2 %0, %1, %2, %3;" : "=l"(d) : "l"(a), "l"(b), "l"(c)); return d;
}
static __device__ __forceinline__ unsigned long long mul2_(unsigned long long a, unsigned long long b) {
    unsigned long long d; asm("mul.rn.f32x2 %0, %1, %2;" : "=l"(d) : "l"(a), "l"(b)); return d;
}
static __device__ __forceinline__ unsigned long long add2_(unsigned long long a, unsigned long long b) {
    unsigned long long d; asm("add.rn.f32x2 %0, %1, %2;" : "=l"(d) : "l"(a), "l"(b)); return d;
}
static __device__ __forceinline__ unsigned int smem_u32(const void* p) {
    unsigned int a; asm("{ .reg .u64 t; cvta.to.shared.u64 t, %1; cvt.u32.u64 %0, t; }" : "=r"(a) : "l"(p)); return a;
}
static __device__ __forceinline__ void cpasync16(unsigned int dst, const void* src) {
    asm volatile("cp.async.ca.shared.global [%0], [%1], 16;" :: "r"(dst), "l"(src));
}
static __device__ __forceinline__ float lds_f(unsigned int a) {
    float v; asm volatile("ld.shared.f32 %0, [%1];" : "=f"(v) : "r"(a)); return v;
}
static __device__ __forceinline__ void lds128(float* d, unsigned int a) {
    asm volatile("ld.shared.v4.f32 {%0,%1,%2,%3}, [%4];"
                 : "=f"(d[0]), "=f"(d[1]), "=f"(d[2]), "=f"(d[3]) : "r"(a));
}
#define CP_COMMIT() asm volatile("cp.async.commit_group;" ::: "memory")
#define CP_WAIT(n)  asm volatile("cp.async.wait_group %0;" :: "n"(n) : "memory")

// x extraction, half0 = floats 0..19 (t = 0,1), half1 = floats 16..35 (t = 2,3)
// sub1's k=4 is the dummy state (E column = 0): index clamped, value irrelevant but finite.
#define X0(A,t,k) (sub ? (A)[(9*(t)+5+(k)) > 19 ? 19 : (9*(t)+5+(k))] : (A)[9*(t)+(k)])
#define X1(A,t,k) (sub ? (A)[(9*(t)+5+(k)-16) > 19 ? 19 : (9*(t)+5+(k)-16)] : (A)[9*(t)+(k)-16])

__global__ __launch_bounds__(128) void crf_fwd_kernel(
    const float* __restrict__ inputs,   // [B, L, 9]
    const int*   __restrict__ path,     // [B, L]
    const float* __restrict__ tran,     // [9, 9]
    const float* __restrict__ initv,    // [9]
    float* __restrict__ out)            // [B]
{
    __shared__ float s_tran[81];
    __shared__ float s_init[9];
    __shared__ __align__(16) char xbuf[SETS * 2 * NBUF * BUF_BYTES];   // 40960 B
    __shared__ float fin[SETS][BPSET][26];                             // 6656 B

    const int tid  = threadIdx.x;
    const int set  = tid >> 6;           // 0,1
    const int w    = (tid >> 5) & 1;     // 0 = fwd (t 0..127), 1 = bwd (t 255..128)
    const int lane = tid & 31;
    const int pair = lane >> 1;          // 0..15
    const int sub  = lane & 1;
    const int b1   = blockIdx.x * BPBLK + set * BPSET + pair;   // chain A batch
    const int b2   = b1 + 16;                                   // chain B batch
    const unsigned FULL = 0xFFFFFFFFu;

    for (int i = tid; i < 81; i += 128) s_tran[i] = tran[i];
    if (tid < 9) s_init[tid] = initv[tid];
    __syncthreads();

    const unsigned int sWbase = smem_u32(xbuf)
        + (unsigned int)(set * 2 + w) * (NBUF * BUF_BYTES);

    const int ownbase = sub * 5;
    const int rembase = 5 - sub * 5;

    // E packs (shared by both chains). fwd: E[src][out]; bwd: E[out][src].
    unsigned long long EoA[5], EoB[5], ErA[5], ErB[5];
    float EoS[5], ErS[5];
    #pragma unroll
    for (int m = 0; m < 5; ++m) {
        int so = ownbase + m, sr = rembase + m;
        float eo[5], er[5];
        #pragma unroll
        for (int k = 0; k < 5; ++k) {
            int o = ownbase + k;
            eo[k] = (so < 9 && o < 9) ? __expf(w ? s_tran[o * 9 + so] : s_tran[so * 9 + o]) : 0.f;
            er[k] = (sr < 9 && o < 9) ? __expf(w ? s_tran[o * 9 + sr] : s_tran[sr * 9 + o]) : 0.f;
        }
        EoA[m] = pk2(eo[0], eo[1]); EoB[m] = pk2(eo[2], eo[3]); EoS[m] = eo[4];
        ErA[m] = pk2(er[0], er[1]); ErB[m] = pk2(er[2], er[3]); ErS[m] = er[4];
    }

    // cp.async descriptors: 32 rows x 9 granules = 288 float4 per group -> 9 per lane exactly
    const char* gbase = (const char*)inputs;
    unsigned int goff[9], sdst[9];
    #pragma unroll
    for (int i = 0; i < 9; ++i) {
        int f4 = lane + 32 * i;
        int bi = f4 / 9, oi = f4 - bi * 9;
        goff[i] = (unsigned int)((blockIdx.x * BPBLK + set * BPSET + bi) * (LL * 9 * 4) + oi * 16);
        sdst[i] = sWbase + (unsigned int)(bi * GRAN + oi) * 16;
    }

    auto issue = [&](int g) {
        unsigned int boff = (unsigned int)(g & 1) * BUF_BYTES;
        #pragma unroll
        for (int i = 0; i < 9; ++i)
            cpasync16(sdst[i] + boff, gbase + goff[i] + (size_t)g * 144);
        CP_COMMIT();
    };

    const unsigned int rowA = sWbase + (unsigned int)pair * ROWB;
    const unsigned int rowB = rowA + 16u * ROWB;

    auto load2 = [&](float* A, unsigned int rowa, int off) {
        #pragma unroll
        for (int i = 0; i < 5; ++i) lds128(A + 4 * i, rowa + off + i * 16);
    };

    const int4* pb4A = (const int4*)(path + (size_t)b1 * LL);
    const int4* pb4B = (const int4*)(path + (size_t)b2 * LL);

    // chain states
    float pA0, pA1, pA2, pA3, pA4, CA = 0.f, emA = 0.f, trA = 0.f;
    float pB0, pB1, pB2, pB3, pB4, CB = 0.f, emB = 0.f, trB = 0.f;
    int ppA, ppB;
    float initA = 0.f, initB = 0.f;

    auto matvec = [&](float y0, float y1, float y2, float y3, float y4,
                      float& n0, float& n1, float& n2, float& n3, float& n4) {
        float r0 = __shfl_xor_sync(FULL, y0, 1);
        float r1 = __shfl_xor_sync(FULL, y1, 1);
        float r2 = __shfl_xor_sync(FULL, y2, 1);
        float r3 = __shfl_xor_sync(FULL, y3, 1);
        float r4 = __shfl_xor_sync(FULL, y4, 1);
        unsigned long long q, A0, A1, B0, B1;
        float a4, b4;
        q = pk2(y0, y0); A0 = mul2_(q, EoA[0]); A1 = mul2_(q, EoB[0]); a4 = y0 * EoS[0];
        q = pk2(y1, y1); A0 = fma2_(q, EoA[1], A0); A1 = fma2_(q, EoB[1], A1); a4 = fmaf(y1, EoS[1], a4);
        q = pk2(y2, y2); A0 = fma2_(q, EoA[2], A0); A1 = fma2_(q, EoB[2], A1); a4 = fmaf(y2, EoS[2], a4);
        q = pk2(y3, y3); A0 = fma2_(q, EoA[3], A0); A1 = fma2_(q, EoB[3], A1); a4 = fmaf(y3, EoS[3], a4);
        q = pk2(y4, y4); A0 = fma2_(q, EoA[4], A0); A1 = fma2_(q, EoB[4], A1); a4 = fmaf(y4, EoS[4], a4);
        q = pk2(r0, r0); B0 = mul2_(q, ErA[0]); B1 = mul2_(q, ErB[0]); b4 = r0 * ErS[0];
        q = pk2(r1, r1); B0 = fma2_(q, ErA[1], B0); B1 = fma2_(q, ErB[1], B1); b4 = fmaf(r1, ErS[1], b4);
        q = pk2(r2, r2); B0 = fma2_(q, ErA[2], B0); B1 = fma2_(q, ErB[2], B1); b4 = fmaf(r2, ErS[2], b4);
        q = pk2(r3, r3); B0 = fma2_(q, ErA[3], B0); B1 = fma2_(q, ErB[3], B1); b4 = fmaf(r3, ErS[3], b4);
        q = pk2(r4, r4); B0 = fma2_(q, ErA[4], B0); B1 = fma2_(q, ErB[4], B1); b4 = fmaf(r4, ErS[4], b4);
        A0 = add2_(A0, B0); A1 = add2_(A1, B1); a4 += b4;
        upk2(n0, n1, A0); upk2(n2, n3, A1); n4 = a4;
    };

    // forward step: q <- e(x) .* (M q);  book split: sub0 emit, sub1 tran
    auto stepf = [&](float& q0, float& q1, float& q2, float& q3, float& q4,
                     float& em, float& tr, int& pp,
                     float x0, float x1, float x2, float x3, float x4,
                     unsigned int xb, int pt) {
        float e0 = __expf(x0), e1 = __expf(x1), e2 = __expf(x2);
        float e3 = __expf(x3), e4 = __expf(x4);
        float n0, n1, n2, n3, n4;
        matvec(q0, q1, q2, q3, q4, n0, n1, n2, n3, n4);
        q0 = n0 * e0; q1 = n1 * e1; q2 = n2 * e2; q3 = n3 * e3; q4 = n4 * e4;
        if (sub == 0) em += lds_f(xb + (unsigned int)(pt * 4));
        else          tr += s_tran[pp * 9 + pt];
        pp = pt;
    };

    // backward step: q <- M (e(x) .* q)
    auto stepb = [&](float& q0, float& q1, float& q2, float& q3, float& q4,
                     float& em, float& tr, int& pp,
                     float x0, float x1, float x2, float x3, float x4,
                     unsigned int xb, int pt) {
        float y0 = q0 * __expf(x0), y1 = q1 * __expf(x1), y2 = q2 * __expf(x2);
        float y3 = q3 * __expf(x3), y4 = q4 * __expf(x4);
        matvec(y0, y1, y2, y3, y4, q0, q1, q2, q3, q4);
        if (sub == 0) em += lds_f(xb + (unsigned int)(pt * 4));
        else          tr += s_tran[pt * 9 + pp];
        pp = pt;
    };

    auto renorm = [&](float& q0, float& q1, float& q2, float& q3, float& q4, float& Cx) {
        float loc = ((q0 + q1) + (q2 + q3)) + q4;
        float s = loc + __shfl_xor_sync(FULL, loc, 1);
        Cx += __logf(s);
        float inv = __fdividef(1.f, s);
        q0 *= inv; q1 *= inv; q2 *= inv; q3 *= inv; q4 *= inv;
    };

    float i0 = (ownbase + 0 < 9) ? s_init[ownbase + 0] : -1e30f;
    float i1 = (ownbase + 1 < 9) ? s_init[ownbase + 1] : -1e30f;
    float i2 = (ownbase + 2 < 9) ? s_init[ownbase + 2] : -1e30f;
    float i3 = (ownbase + 3 < 9) ? s_init[ownbase + 3] : -1e30f;
    float i4 = (ownbase + 4 < 9) ? s_init[ownbase + 4] : -1e30f;

    if (w == 0) {
        // ========== forward: groups 0..31 ==========
        issue(0);
        #pragma unroll 1
        for (int g = 0; g <= 31; ++g) {
            CP_WAIT(0); __syncwarp();
            if (g < 31) issue(g + 1);
            unsigned int boff = (unsigned int)(g & 1) * BUF_BYTES;
            unsigned int ra = rowA + boff, rb = rowB + boff;
            int4 PA = pb4A[g], PB = pb4B[g];
            float fa[20], fb[20];
            load2(fa, ra, 0); load2(fb, rb, 0);

            if (g == 0) {
                pA0 = __expf(i0 + X0(fa,0,0)); pA1 = __expf(i1 + X0(fa,0,1));
                pA2 = __expf(i2 + X0(fa,0,2)); pA3 = __expf(i3 + X0(fa,0,3));
                pA4 = __expf(i4 + X0(fa,0,4));
                pB0 = __expf(i0 + X0(fb,0,0)); pB1 = __expf(i1 + X0(fb,0,1));
                pB2 = __expf(i2 + X0(fb,0,2)); pB3 = __expf(i3 + X0(fb,0,3));
                pB4 = __expf(i4 + X0(fb,0,4));
                ppA = PA.x; ppB = PB.x;
                if (sub == 0) { emA = lds_f(ra + (unsigned int)(PA.x * 4));
                                emB = lds_f(rb + (unsigned int)(PB.x * 4)); }
                initA = s_init[PA.x]; initB = s_init[PB.x];
            } else {
                stepf(pA0,pA1,pA2,pA3,pA4, emA,trA,ppA,
                      X0(fa,0,0),X0(fa,0,1),X0(fa,0,2),X0(fa,0,3),X0(fa,0,4), ra, PA.x);
                stepf(pB0,pB1,pB2,pB3,pB4, emB,trB,ppB,
                      X0(fb,0,0),X0(fb,0,1),X0(fb,0,2),X0(fb,0,3),X0(fb,0,4), rb, PB.x);
            }
            stepf(pA0,pA1,pA2,pA3,pA4, emA,trA,ppA,
                  X0(fa,1,0),X0(fa,1,1),X0(fa,1,2),X0(fa,1,3),X0(fa,1,4), ra + 36, PA.y);
            stepf(pB0,pB1,pB2,pB3,pB4, emB,trB,ppB,
                  X0(fb,1,0),X0(fb,1,1),X0(fb,1,2),X0(fb,1,3),X0(fb,1,4), rb + 36, PB.y);

            float ga[20], gb[20];
            load2(ga, ra, 64); load2(gb, rb, 64);
            stepf(pA0,pA1,pA2,pA3,pA4, emA,trA,ppA,
                  X1(ga,2,0),X1(ga,2,1),X1(ga,2,2),X1(ga,2,3),X1(ga,2,4), ra + 72, PA.z);
            stepf(pB0,pB1,pB2,pB3,pB4, emB,trB,ppB,
                  X1(gb,2,0),X1(gb,2,1),X1(gb,2,2),X1(gb,2,3),X1(gb,2,4), rb + 72, PB.z);
            stepf(pA0,pA1,pA2,pA3,pA4, emA,trA,ppA,
                  X1(ga,3,0),X1(ga,3,1),X1(ga,3,2),X1(ga,3,3),X1(ga,3,4), ra + 108, PA.w);
            stepf(pB0,pB1,pB2,pB3,pB4, emB,trB,ppB,
                  X1(gb,3,0),X1(gb,3,1),X1(gb,3,2),X1(gb,3,3),X1(gb,3,4), rb + 108, PB.w);

            if ((g & 1) && g < 31) {
                renorm(pA0,pA1,pA2,pA3,pA4, CA);
                renorm(pB0,pB1,pB2,pB3,pB4, CB);
            }
        }

        float scA = emA + trA; scA += __shfl_xor_sync(FULL, scA, 1);
        float scB = emB + trB; scB += __shfl_xor_sync(FULL, scB, 1);
        if (sub == 0) {
            fin[set][pair][0] = pA0; fin[set][pair][1] = pA1; fin[set][pair][2] = pA2;
            fin[set][pair][3] = pA3; fin[set][pair][4] = pA4;
            fin[set][pair][9]  = CA; fin[set][pair][10] = scA + initA;
            fin[set][pair][11] = __int_as_float(ppA);
            fin[set][pair+16][0] = pB0; fin[set][pair+16][1] = pB1; fin[set][pair+16][2] = pB2;
            fin[set][pair+16][3] = pB3; fin[set][pair+16][4] = pB4;
            fin[set][pair+16][9]  = CB; fin[set][pair+16][10] = scB + initB;
            fin[set][pair+16][11] = __int_as_float(ppB);
        } else {
            fin[set][pair][5] = pA0; fin[set][pair][6] = pA1;
            fin[set][pair][7] = pA2; fin[set][pair][8] = pA3;
            fin[set][pair+16][5] = pB0; fin[set][pair+16][6] = pB1;
            fin[set][pair+16][7] = pB2; fin[set][pair+16][8] = pB3;
        }
    } else {
        // ========== backward: groups 63..32 ==========
        issue(63);
        #pragma unroll 1
        for (int k = 0; k <= 31; ++k) {
            int g = 63 - k;
            CP_WAIT(0); __syncwarp();
            if (k < 31) issue(g - 1);
            unsigned int boff = (unsigned int)(g & 1) * BUF_BYTES;
            unsigned int ra = rowA + boff, rb = rowB + boff;
            int4 PA = pb4A[g], PB = pb4B[g];
            float ga[20], gb[20];
            load2(ga, ra, 64); load2(gb, rb, 64);

            if (g == 63) {
                // init: p = E * exp(x_255) = beta_254
                pA0 = (ownbase + 0 < 9) ? __expf(X1(ga,3,0)) : 0.f;
                pA1 = (ownbase + 1 < 9) ? __expf(X1(ga,3,1)) : 0.f;
                pA2 = (ownbase + 2 < 9) ? __expf(X1(ga,3,2)) : 0.f;
                pA3 = (ownbase + 3 < 9) ? __expf(X1(ga,3,3)) : 0.f;
                pA4 = (ownbase + 4 < 9) ? __expf(X1(ga,3,4)) : 0.f;
                matvec(pA0,pA1,pA2,pA3,pA4, pA0,pA1,pA2,pA3,pA4);
                pB0 = (ownbase + 0 < 9) ? __expf(X1(gb,3,0)) : 0.f;
                pB1 = (ownbase + 1 < 9) ? __expf(X1(gb,3,1)) : 0.f;
                pB2 = (ownbase + 2 < 9) ? __expf(X1(gb,3,2)) : 0.f;
                pB3 = (ownbase + 3 < 9) ? __expf(X1(gb,3,3)) : 0.f;
                pB4 = (ownbase + 4 < 9) ? __expf(X1(gb,3,4)) : 0.f;
                matvec(pB0,pB1,pB2,pB3,pB4, pB0,pB1,pB2,pB3,pB4);
                ppA = PA.w; ppB = PB.w;
                if (sub == 0) { emA = lds_f(ra + 108 + (unsigned int)(PA.w * 4));
                                emB = lds_f(rb + 108 + (unsigned int)(PB.w * 4)); }
            } else {
                stepb(pA0,pA1,pA2,pA3,pA4, emA,trA,ppA,
                      X1(ga,3,0),X1(ga,3,1),X1(ga,3,2),X1(ga,3,3),X1(ga,3,4), ra + 108, PA.w);
                stepb(pB0,pB1,pB2,pB3,pB4, emB,trB,ppB,
                      X1(gb,3,0),X1(gb,3,1),X1(gb,3,2),X1(gb,3,3),X1(gb,3,4), rb + 108, PB.w);
            }
            stepb(pA0,pA1,pA2,pA3,pA4, emA,trA,ppA,
                  X1(ga,2,0),X1(ga,2,1),X1(ga,2,2),X1(ga,2,3),X1(ga,2,4), ra + 72, PA.z);
            stepb(pB0,pB1,pB2,pB3,pB4, emB,trB,ppB,
                  X1(gb,2,0),X1(gb,2,1),X1(gb,2,2),X1(gb,2,3),X1(gb,2,4), rb + 72, PB.z);

            float fa[20], fb[20];
            load2(fa, ra, 0); load2(fb, rb, 0);
            stepb(pA0,pA1,pA2,pA3,pA4, emA,trA,ppA,
                  X0(fa,1,0),X0(fa,1,1),X0(fa,1,2),X0(fa,1,3),X0(fa,1,4), ra + 36, PA.y);
            stepb(pB0,pB1,pB2,pB3,pB4, emB,trB,ppB,
                  X0(fb,1,0),X0(fb,1,1),X0(fb,1,2),X0(fb,1,3),X0(fb,1,4), rb + 36, PB.y);
            stepb(pA0,pA1,pA2,pA3,pA4, emA,trA,ppA,
                  X0(fa,0,0),X0(fa,0,1),X0(fa,0,2),X0(fa,0,3),X0(fa,0,4), ra, PA.x);
            stepb(pB0,pB1,pB2,pB3,pB4, emB,trB,ppB,
                  X0(fb,0,0),X0(fb,0,1),X0(fb,0,2),X0(fb,0,3),X0(fb,0,4), rb, PB.x);

            if (((g & 1) == 0) && g > 32) {
                renorm(pA0,pA1,pA2,pA3,pA4, CA);
                renorm(pB0,pB1,pB2,pB3,pB4, CB);
            }
        }

        float scA = emA + trA; scA += __shfl_xor_sync(FULL, scA, 1);
        float scB = emB + trB; scB += __shfl_xor_sync(FULL, scB, 1);
        if (sub == 0) {
            fin[set][pair][12] = pA0; fin[set][pair][13] = pA1; fin[set][pair][14] = pA2;
            fin[set][pair][15] = pA3; fin[set][pair][16] = pA4;
            fin[set][pair][21] = CA; fin[set][pair][22] = scA;
            fin[set][pair][23] = __int_as_float(ppA);
            fin[set][pair+16][12] = pB0; fin[set][pair+16][13] = pB1; fin[set][pair+16][14] = pB2;
            fin[set][pair+16][15] = pB3; fin[set][pair+16][16] = pB4;
            fin[set][pair+16][21] = CB; fin[set][pair+16][22] = scB;
            fin[set][pair+16][23] = __int_as_float(ppB);
        } else {
            fin[set][pair][17] = pA0; fin[set][pair][18] = pA1;
            fin[set][pair][19] = pA2; fin[set][pair][20] = pA3;
            fin[set][pair+16][17] = pB0; fin[set][pair+16][18] = pB1;
            fin[set][pair+16][19] = pB2; fin[set][pair+16][20] = pB3;
        }
    }

    __syncthreads();

    // combine: per set, sub==0 lanes of the forward warp handle rows pair and pair+16
    if (w == 0 && sub == 0) {
        #pragma unroll
        for (int h = 0; h < 2; ++h) {
            int r = pair + 16 * h;
            int bb = (h == 0) ? b1 : b2;
            float dot = 0.f;
            #pragma unroll
            for (int i = 0; i < 9; ++i) dot = fmaf(fin[set][r][i], fin[set][r][12 + i], dot);
            float logZ = fin[set][r][9] + fin[set][r][21] + __logf(dot);
            int pa = __float_as_int(fin[set][r][11]);
            int pb = __float_as_int(fin[set][r][23]);
            float score = fin[set][r][10] + fin[set][r][22] + s_tran[pa * 9 + pb];
            out[bb] = logZ - score;
        }
    }
}

extern "C" void kernel_launch(void* const* d_in, const int* in_sizes, int n_in,
                              void* d_out, int out_size) {
    (void)in_sizes; (void)n_in; (void)out_size;
    const float* inputs = (const float*)d_in[0];
    const int*   path   = (const int*)d_in[1];
    const float* tran   = (const float*)d_in[2];
    const float* initv  = (const float*)d_in[3];
    float* out = (float*)d_out;

    crf_fwd_kernel<<<BB / BPBLK, 128>>>(inputs, path, tran, initv, out);
}

// round 13
// speedup vs baseline: 1.3101x; 1.3101x over previous
#include <cuda_runtime.h>
#include <cuda_bf16.h>
#include <cstdint>

#define BB 8192
#define LL 256
#define NBUF 2
#define ROWB 144                      // 9 granules * 16B, conflict-free stride for LDS.128
#define WARP_BUF (32 * ROWB)          // 4608 B
#define WARP_SMEM (NBUF * WARP_BUF)   // 9216 B

static __device__ __forceinline__ unsigned long long pk2(float lo, float hi) {
    unsigned long long r; asm("mov.b64 %0, {%1,%2};" : "=l"(r) : "f"(lo), "f"(hi)); return r;
}
static __device__ __forceinline__ void upk2(float& lo, float& hi, unsigned long long v) {
    asm("mov.b64 {%0,%1}, %2;" : "=f"(lo), "=f"(hi) : "l"(v));
}
static __device__ __forceinline__ unsigned long long fma2_(unsigned long long a, unsigned long long b, unsigned long long c) {
    unsigned long long d; asm("fma.rn.f32x2 %0, %1, %2, %3;" : "=l"(d) : "l"(a), "l"(b), "l"(c)); return d;
}
static __device__ __forceinline__ unsigned long long mul2_(unsigned long long a, unsigned long long b) {
    unsigned long long d; asm("mul.rn.f32x2 %0, %1, %2;" : "=l"(d) : "l"(a), "l"(b)); return d;
}
static __device__ __forceinline__ unsigned long long add2_(unsigned long long a, unsigned long long b) {
    unsigned long long d; asm("add.rn.f32x2 %0, %1, %2;" : "=l"(d) : "l"(a), "l"(b)); return d;
}
static __device__ __forceinline__ unsigned int smem_u32(const void* p) {
    unsigned int a; asm("{ .reg .u64 t; cvta.to.shared.u64 t, %1; cvt.u32.u64 %0, t; }" : "=r"(a) : "l"(p)); return a;
}
static __device__ __forceinline__ void cpasync16(unsigned int dst, const void* src) {
    asm volatile("cp.async.ca.shared.global [%0], [%1], 16;" :: "r"(dst), "l"(src));
}
static __device__ __forceinline__ float lds_f(unsigned int a) {
    float v; asm volatile("ld.shared.f32 %0, [%1];" : "=f"(v) : "r"(a)); return v;
}
#define CP_COMMIT() asm volatile("cp.async.commit_group;" ::: "memory")
#define CP_WAIT(n)  asm volatile("cp.async.wait_group %0;" :: "n"(n) : "memory")

__global__ __launch_bounds__(128) void crf_fwd_kernel(
    const float* __restrict__ inputs,   // [B, L, 9]
    const int*   __restrict__ path,     // [B, L]
    const float* __restrict__ tran,     // [9, 9]
    const float* __restrict__ initv,    // [9]
    float* __restrict__ out)            // [B]
{
    __shared__ float s_tran[81];
    __shared__ float s_init[9];
    __shared__ __align__(16) char xbuf[4 * WARP_SMEM];   // 36864 B
    __shared__ float fin[64][26];                        // 6656 B

    const int tid  = threadIdx.x;
    const int w    = tid >> 5;
    const int lane = tid & 31;
    const int dir  = w & 1;              // 0 = fwd (t 0..127), 1 = bwd (t 255..128)
    const int half = w >> 1;             // 0,1 : which 32-batch subset
    const int b    = blockIdx.x * 64 + half * 32 + lane;
    const int frow = half * 32 + lane;   // fin row

    for (int i = tid; i < 81; i += 128) s_tran[i] = tran[i];
    if (tid < 9) s_init[tid] = initv[tid];
    __syncthreads();

    // E packs per lane. fwd: M[s][o] = exp(tran[s][o]); bwd: M[s][o] = exp(tran[o][s]).
    unsigned long long Epk[9][4];
    float Ek8[9];
    #pragma unroll
    for (int k = 0; k < 9; ++k) {
        float e[9];
        #pragma unroll
        for (int o = 0; o < 9; ++o)
            e[o] = __expf(dir ? s_tran[o * 9 + k] : s_tran[k * 9 + o]);
        Epk[k][0] = pk2(e[0], e[1]); Epk[k][1] = pk2(e[2], e[3]);
        Epk[k][2] = pk2(e[4], e[5]); Epk[k][3] = pk2(e[6], e[7]);
        Ek8[k] = e[8];
    }

    // cp.async: 32 batches x 9 granules = 288 float4 per group -> exactly 9 per lane
    const unsigned int wbase = smem_u32(xbuf) + (unsigned int)w * WARP_SMEM;
    const char* gsrc[9];
    unsigned int sdst[9];
    #pragma unroll
    for (int i = 0; i < 9; ++i) {
        int f4 = lane + 32 * i;
        int bi = f4 / 9, oi = f4 - bi * 9;
        gsrc[i] = (const char*)inputs
                + (size_t)(blockIdx.x * 64 + half * 32 + bi) * (LL * 9 * 4) + oi * 16;
        sdst[i] = wbase + (unsigned int)(bi * ROWB + oi * 16);
    }
    auto issue = [&](int g) {
        unsigned int boff = (unsigned int)(g & 1) * WARP_BUF;
        #pragma unroll
        for (int i = 0; i < 9; ++i)
            cpasync16(sdst[i] + boff, gsrc[i] + (size_t)g * 144);
        CP_COMMIT();
    };

    const unsigned int myrow = wbase + (unsigned int)lane * ROWB;
    float4 X[9];
    auto loadX = [&](int g) {
        unsigned int a = myrow + (unsigned int)(g & 1) * WARP_BUF;
        #pragma unroll
        for (int i = 0; i < 9; ++i)
            asm volatile("ld.shared.v4.f32 {%0,%1,%2,%3}, [%4];"
                         : "=f"(X[i].x), "=f"(X[i].y), "=f"(X[i].z), "=f"(X[i].w)
                         : "r"(a + i * 16));
    };

    const int4* pb4 = (const int4*)(path + (size_t)b * LL);

    float p0,p1,p2,p3,p4,p5,p6,p7,p8;
    float C = 0.f, emit = 0.f, tracc = 0.f;
    int ptp;

    // 9x9 matvec: n_o = sum_s y_s * M[s][o]
    auto matvec = [&](float y0, float y1, float y2, float y3, float y4,
                      float y5, float y6, float y7, float y8,
                      float& n0, float& n1, float& n2, float& n3, float& n4,
                      float& n5, float& n6, float& n7, float& n8) {
        unsigned long long q, A0, A1, A2, A3, B0, B1, B2, B3;
        float a8, b8;
        q = pk2(y0,y0);
        A0 = mul2_(q, Epk[0][0]); A1 = mul2_(q, Epk[0][1]);
        A2 = mul2_(q, Epk[0][2]); A3 = mul2_(q, Epk[0][3]);
        a8 = y0 * Ek8[0];
        q = pk2(y1,y1);
        A0 = fma2_(q, Epk[1][0], A0); A1 = fma2_(q, Epk[1][1], A1);
        A2 = fma2_(q, Epk[1][2], A2); A3 = fma2_(q, Epk[1][3], A3);
        a8 = fmaf(y1, Ek8[1], a8);
        q = pk2(y2,y2);
        A0 = fma2_(q, Epk[2][0], A0); A1 = fma2_(q, Epk[2][1], A1);
        A2 = fma2_(q, Epk[2][2], A2); A3 = fma2_(q, Epk[2][3], A3);
        a8 = fmaf(y2, Ek8[2], a8);
        q = pk2(y3,y3);
        A0 = fma2_(q, Epk[3][0], A0); A1 = fma2_(q, Epk[3][1], A1);
        A2 = fma2_(q, Epk[3][2], A2); A3 = fma2_(q, Epk[3][3], A3);
        a8 = fmaf(y3, Ek8[3], a8);
        q = pk2(y4,y4);
        B0 = mul2_(q, Epk[4][0]); B1 = mul2_(q, Epk[4][1]);
        B2 = mul2_(q, Epk[4][2]); B3 = mul2_(q, Epk[4][3]);
        b8 = y4 * Ek8[4];
        q = pk2(y5,y5);
        B0 = fma2_(q, Epk[5][0], B0); B1 = fma2_(q, Epk[5][1], B1);
        B2 = fma2_(q, Epk[5][2], B2); B3 = fma2_(q, Epk[5][3], B3);
        b8 = fmaf(y5, Ek8[5], b8);
        q = pk2(y6,y6);
        B0 = fma2_(q, Epk[6][0], B0); B1 = fma2_(q, Epk[6][1], B1);
        B2 = fma2_(q, Epk[6][2], B2); B3 = fma2_(q, Epk[6][3], B3);
        b8 = fmaf(y6, Ek8[6], b8);
        q = pk2(y7,y7);
        B0 = fma2_(q, Epk[7][0], B0); B1 = fma2_(q, Epk[7][1], B1);
        B2 = fma2_(q, Epk[7][2], B2); B3 = fma2_(q, Epk[7][3], B3);
        b8 = fmaf(y7, Ek8[7], b8);
        q = pk2(y8,y8);
        B0 = fma2_(q, Epk[8][0], B0); B1 = fma2_(q, Epk[8][1], B1);
        B2 = fma2_(q, Epk[8][2], B2); B3 = fma2_(q, Epk[8][3], B3);
        b8 = fmaf(y8, Ek8[8], b8);
        A0 = add2_(A0, B0); A1 = add2_(A1, B1);
        A2 = add2_(A2, B2); A3 = add2_(A3, B3);
        a8 += b8;
        upk2(n0, n1, A0); upk2(n2, n3, A1);
        upk2(n4, n5, A2); upk2(n6, n7, A3);
        n8 = a8;
    };

    auto stepf = [&](float x0, float x1, float x2, float x3, float x4,
                     float x5, float x6, float x7, float x8,
                     unsigned int xb, int pt) {
        float e0=__expf(x0), e1=__expf(x1), e2=__expf(x2), e3=__expf(x3), e4=__expf(x4);
        float e5=__expf(x5), e6=__expf(x6), e7=__expf(x7), e8=__expf(x8);
        float n0,n1,n2,n3,n4,n5,n6,n7,n8;
        matvec(p0,p1,p2,p3,p4,p5,p6,p7,p8, n0,n1,n2,n3,n4,n5,n6,n7,n8);
        p0=n0*e0; p1=n1*e1; p2=n2*e2; p3=n3*e3; p4=n4*e4;
        p5=n5*e5; p6=n6*e6; p7=n7*e7; p8=n8*e8;
        emit  += lds_f(xb + (unsigned int)(pt * 4));
        tracc += s_tran[ptp * 9 + pt];
        ptp = pt;
    };

    auto stepb = [&](float x0, float x1, float x2, float x3, float x4,
                     float x5, float x6, float x7, float x8,
                     unsigned int xb, int pt) {
        float y0=p0*__expf(x0), y1=p1*__expf(x1), y2=p2*__expf(x2);
        float y3=p3*__expf(x3), y4=p4*__expf(x4), y5=p5*__expf(x5);
        float y6=p6*__expf(x6), y7=p7*__expf(x7), y8=p8*__expf(x8);
        matvec(y0,y1,y2,y3,y4,y5,y6,y7,y8, p0,p1,p2,p3,p4,p5,p6,p7,p8);
        emit  += lds_f(xb + (unsigned int)(pt * 4));
        tracc += s_tran[pt * 9 + ptp];
        ptp = pt;
    };

    auto renorm = [&]() {
        float s = (((p0+p1)+(p2+p3)) + ((p4+p5)+(p6+p7))) + p8;
        C += __logf(s);
        float inv = __fdividef(1.f, s);
        p0*=inv; p1*=inv; p2*=inv; p3*=inv; p4*=inv;
        p5*=inv; p6*=inv; p7*=inv; p8*=inv;
    };

    if (dir == 0) {
        // ===== forward: groups 0..31 (t = 0..127) =====
        issue(0);
        float initterm = 0.f;
        #pragma unroll 1
        for (int g = 0; g <= 31; ++g) {
            CP_WAIT(0); __syncwarp();
            if (g < 31) issue(g + 1);
            loadX(g);
            int4 P = pb4[g];
            unsigned int xb = myrow + (unsigned int)(g & 1) * WARP_BUF;

            if (g == 0) {
                p0 = __expf(s_init[0] + X[0].x);
                p1 = __expf(s_init[1] + X[0].y);
                p2 = __expf(s_init[2] + X[0].z);
                p3 = __expf(s_init[3] + X[0].w);
                p4 = __expf(s_init[4] + X[1].x);
                p5 = __expf(s_init[5] + X[1].y);
                p6 = __expf(s_init[6] + X[1].z);
                p7 = __expf(s_init[7] + X[1].w);
                p8 = __expf(s_init[8] + X[2].x);
                ptp = P.x;
                emit = lds_f(xb + (unsigned int)(P.x * 4));
                initterm = s_init[P.x];
            } else {
                stepf(X[0].x,X[0].y,X[0].z,X[0].w, X[1].x,X[1].y,X[1].z,X[1].w, X[2].x,
                      xb, P.x);
            }
            stepf(X[2].y,X[2].z,X[2].w, X[3].x,X[3].y,X[3].z,X[3].w, X[4].x,X[4].y,
                  xb + 36, P.y);
            stepf(X[4].z,X[4].w, X[5].x,X[5].y,X[5].z,X[5].w, X[6].x,X[6].y,X[6].z,
                  xb + 72, P.z);
            stepf(X[6].w, X[7].x,X[7].y,X[7].z,X[7].w, X[8].x,X[8].y,X[8].z,X[8].w,
                  xb + 108, P.w);

            if (g & 1) renorm();
        }
        fin[frow][0]=p0; fin[frow][1]=p1; fin[frow][2]=p2; fin[frow][3]=p3;
        fin[frow][4]=p4; fin[frow][5]=p5; fin[frow][6]=p6; fin[frow][7]=p7;
        fin[frow][8]=p8;
        fin[frow][9]  = C;
        fin[frow][10] = emit + initterm + tracc;
        fin[frow][11] = __int_as_float(ptp);
    } else {
        // ===== backward: groups 63..32 (t = 255..128) =====
        issue(63);
        #pragma unroll 1
        for (int k = 0; k <= 31; ++k) {
            int g = 63 - k;
            CP_WAIT(0); __syncwarp();
            if (k < 31) issue(g - 1);
            loadX(g);
            int4 P = pb4[g];
            unsigned int xb = myrow + (unsigned int)(g & 1) * WARP_BUF;

            if (g == 63) {
                // init: p = E * exp(x_255) = beta_254
                p0 = __expf(X[6].w); p1 = __expf(X[7].x); p2 = __expf(X[7].y);
                p3 = __expf(X[7].z); p4 = __expf(X[7].w); p5 = __expf(X[8].x);
                p6 = __expf(X[8].y); p7 = __expf(X[8].z); p8 = __expf(X[8].w);
                matvec(p0,p1,p2,p3,p4,p5,p6,p7,p8, p0,p1,p2,p3,p4,p5,p6,p7,p8);
                ptp = P.w;
                emit = lds_f(xb + 108 + (unsigned int)(P.w * 4));
            } else {
                stepb(X[6].w, X[7].x,X[7].y,X[7].z,X[7].w, X[8].x,X[8].y,X[8].z,X[8].w,
                      xb + 108, P.w);
            }
            stepb(X[4].z,X[4].w, X[5].x,X[5].y,X[5].z,X[5].w, X[6].x,X[6].y,X[6].z,
                  xb + 72, P.z);
            stepb(X[2].y,X[2].z,X[2].w, X[3].x,X[3].y,X[3].z,X[3].w, X[4].x,X[4].y,
                  xb + 36, P.y);
            stepb(X[0].x,X[0].y,X[0].z,X[0].w, X[1].x,X[1].y,X[1].z,X[1].w, X[2].x,
                  xb, P.x);

            if ((g & 1) == 0) renorm();
        }
        fin[frow][12]=p0; fin[frow][13]=p1; fin[frow][14]=p2; fin[frow][15]=p3;
        fin[frow][16]=p4; fin[frow][17]=p5; fin[frow][18]=p6; fin[frow][19]=p7;
        fin[frow][20]=p8;
        fin[frow][21] = C;
        fin[frow][22] = emit + tracc;
        fin[frow][23] = __int_as_float(ptp);
    }

    __syncthreads();

    // combine: forward warps handle their own batch
    if (dir == 0) {
        float dot = 0.f;
        #pragma unroll
        for (int i = 0; i < 9; ++i)
            dot = fmaf(fin[frow][i], fin[frow][12 + i], dot);
        float logZ = fin[frow][9] + fin[frow][21] + __logf(dot);
        int pa = __float_as_int(fin[frow][11]);
        int pb = __float_as_int(fin[frow][23]);
        float score = fin[frow][10] + fin[frow][22] + s_tran[pa * 9 + pb];
        out[b] = logZ - score;
    }
}

extern "C" void kernel_launch(void* const* d_in, const int* in_sizes, int n_in,
                              void* d_out, int out_size) {
    (void)in_sizes; (void)n_in; (void)out_size;
    const float* inputs = (const float*)d_in[0];
    const int*   path   = (const int*)d_in[1];
    const float* tran   = (const float*)d_in[2];
    const float* initv  = (const float*)d_in[3];
    float* out = (float*)d_out;

    crf_fwd_kernel<<<BB / 64, 128>>>(inputs, path, tran, initv, out);
}